// round 1
// baseline (speedup 1.0000x reference)
#include <cuda_runtime.h>
#include <cstdint>

// Problem constants (from reference): B=1024, L=512, T=50 (48 tags + START + STOP)
#define T_TAGS   50
#define T_PAD    52          // padded to multiple of 4 for float4
#define START_TAG 48
#define STOP_TAG  49
#define NEG_VAL  (-10000.0f)
#define PADNEG   (-1e30f)

// Scratch (allocation-free rule: __device__ globals)
__device__ __align__(16) float g_E[64 * T_PAD];   // exp(trans - rowmax), rows >=50 zero
__device__ float g_M[64];                          // row max of trans
__device__ float g_tstop[64];                      // transitions[STOP][y], pad = -1e30
__device__ float g_partial[4096];                  // per-batch (partition - emission - trans)

// ---------------------------------------------------------------------------
// Kernel 1: precompute E, M, tstop from transitions (one 64-thread block)
// ---------------------------------------------------------------------------
__global__ void crf_prep(const float* __restrict__ trans) {
    int y = threadIdx.x;   // 0..63
    float M = PADNEG;
    if (y < T_TAGS) {
        #pragma unroll 10
        for (int x = 0; x < T_TAGS; ++x)
            M = fmaxf(M, trans[y * T_TAGS + x]);
    }
    g_M[y] = (y < T_TAGS) ? M : 0.0f;
    for (int x = 0; x < T_PAD; ++x) {
        float e = 0.0f;
        if (y < T_TAGS && x < T_TAGS)
            e = __expf(trans[y * T_TAGS + x] - M);
        g_E[y * T_PAD + x] = e;
    }
    g_tstop[y] = (y < T_TAGS) ? trans[STOP_TAG * T_TAGS + y] : PADNEG;
}

// ---------------------------------------------------------------------------
// Kernel 2: one block per batch element. 64 threads; thread y owns tag y.
// ---------------------------------------------------------------------------
__global__ __launch_bounds__(64) void crf_main(
    const float* __restrict__ logits,
    const float* __restrict__ trans,
    const int*   __restrict__ labels,
    const int*   __restrict__ lens,
    int L)
{
    const int b = blockIdx.x;
    const int y = threadIdx.x;
    const int lane = y & 31;
    const int warp = y >> 5;

    const int len = lens[b];
    const float* lg  = logits + (size_t)b * (size_t)L * T_TAGS;
    const int*   lab = labels + (size_t)b * L;

    __shared__ float s_red[64];
    __shared__ float s_wm[2];
    __shared__ __align__(16) float s_a[T_PAD];

    // ---- emission + transition gold score (parallel over l) ----
    float acc = 0.0f;
    for (int l = y; l < len; l += 64) {
        int cur  = lab[l];
        acc += lg[l * T_TAGS + cur];
        int prev = (l == 0) ? START_TAG : lab[l - 1];
        acc += trans[cur * T_TAGS + prev];
    }
    if (y == 0) acc += trans[STOP_TAG * T_TAGS + lab[len - 1]];
    s_red[y] = acc;
    __syncthreads();
    #pragma unroll
    for (int s = 32; s > 0; s >>= 1) {
        if (y < s) s_red[y] += s_red[y + s];
        __syncthreads();
    }
    float gold = s_red[0];   // valid in all threads after the sync above
    __syncthreads();         // allow s_red reuse below

    // ---- load E row into registers (13 x float4, conflict-free) ----
    float Er[T_PAD];
    #pragma unroll
    for (int i = 0; i < T_PAD / 4; ++i) {
        float4 v = *reinterpret_cast<const float4*>(&g_E[y * T_PAD + i * 4]);
        Er[i * 4 + 0] = v.x;
        Er[i * 4 + 1] = v.y;
        Er[i * 4 + 2] = v.z;
        Er[i * 4 + 3] = v.w;
    }
    const float My    = g_M[y];
    const float tstop = g_tstop[y];

    // ---- forward recurrence in exp domain ----
    // alpha init: NEG everywhere, 0 at START; pad lanes hard -inf-ish
    float alpha = (y == START_TAG) ? 0.0f : ((y < T_TAGS) ? NEG_VAL : PADNEG);

    for (int l = 0; l < len; ++l) {
        // prefetch logit for this step (latency hidden behind reduction/syncs)
        float lgt = 0.0f;
        if (y < T_TAGS) lgt = __ldg(&lg[l * T_TAGS + y]);

        // m = max_x alpha[x]  (warp shuffle + 2-slot shared exchange)
        float wm = alpha;
        #pragma unroll
        for (int o = 16; o > 0; o >>= 1)
            wm = fmaxf(wm, __shfl_xor_sync(0xFFFFFFFFu, wm, o));
        if (lane == 0) s_wm[warp] = wm;
        __syncthreads();                       // SYNC1: wm published; prev a reads done
        float m = fmaxf(s_wm[0], s_wm[1]);

        // publish a[x] = exp(alpha - m); pad lanes produce exact 0
        float av = __expf(alpha - m);
        if (y < T_PAD) s_a[y] = av;
        __syncthreads();                       // SYNC2: a published

        // dot = E[y] . a   (13 x LDS.128 broadcast + 52 FFMA, 4 accumulators)
        float d0 = 0.f, d1 = 0.f, d2 = 0.f, d3 = 0.f;
        #pragma unroll
        for (int i = 0; i < T_PAD / 4; ++i) {
            float4 a4 = *reinterpret_cast<const float4*>(&s_a[i * 4]);
            d0 = fmaf(Er[i * 4 + 0], a4.x, d0);
            d1 = fmaf(Er[i * 4 + 1], a4.y, d1);
            d2 = fmaf(Er[i * 4 + 2], a4.z, d2);
            d3 = fmaf(Er[i * 4 + 3], a4.w, d3);
        }
        float dot = (d0 + d1) + (d2 + d3);

        if (y < T_TAGS)
            alpha = lgt + My + m + __logf(dot);
    }

    // ---- partition = LSE_y(alpha + trans[STOP][y]) ----
    float v = (y < T_TAGS) ? (alpha + tstop) : PADNEG;
    s_red[y] = v;
    __syncthreads();
    #pragma unroll
    for (int s = 32; s > 0; s >>= 1) {
        if (y < s) s_red[y] = fmaxf(s_red[y], s_red[y + s]);
        __syncthreads();
    }
    float m2 = s_red[0];
    __syncthreads();
    s_red[y] = __expf(v - m2);
    __syncthreads();
    #pragma unroll
    for (int s = 32; s > 0; s >>= 1) {
        if (y < s) s_red[y] += s_red[y + s];
        __syncthreads();
    }
    if (y == 0) {
        float partition = m2 + __logf(s_red[0]);
        g_partial[b] = partition - gold;
    }
}

// ---------------------------------------------------------------------------
// Kernel 3: deterministic final reduction -> scalar mean
// ---------------------------------------------------------------------------
__global__ void crf_reduce(float* __restrict__ out, int B) {
    __shared__ float s[256];
    float a = 0.0f;
    for (int i = threadIdx.x; i < B; i += 256) a += g_partial[i];
    s[threadIdx.x] = a;
    __syncthreads();
    #pragma unroll
    for (int st = 128; st > 0; st >>= 1) {
        if (threadIdx.x < st) s[threadIdx.x] += s[threadIdx.x + st];
        __syncthreads();
    }
    if (threadIdx.x == 0) out[0] = s[0] / (float)B;
}

// ---------------------------------------------------------------------------
extern "C" void kernel_launch(void* const* d_in, const int* in_sizes, int n_in,
                              void* d_out, int out_size)
{
    // Identify inputs by element count (robust to metadata ordering):
    //   logits: B*L*T = 26,214,400   transitions: T*T = 2,500
    //   labels: B*L   = 524,288      lens: B = 1,024
    const float* logits = nullptr;
    const float* trans  = nullptr;
    const int*   labels = nullptr;
    const int*   lens   = nullptr;
    int B = 1024, L = 512;

    long long sz[8];
    for (int i = 0; i < n_in && i < 8; ++i) sz[i] = in_sizes[i];

    int i_logits = -1, i_trans = -1, i_labels = -1, i_lens = -1;
    // lens = smallest, trans = T*T (2500), labels = B*L, logits = largest
    long long mx = -1, mn = (long long)1 << 62;
    for (int i = 0; i < n_in; ++i) {
        if (sz[i] > mx) { mx = sz[i]; i_logits = i; }
        if (sz[i] < mn) { mn = sz[i]; i_lens = i; }
    }
    for (int i = 0; i < n_in; ++i) {
        if (i == i_logits || i == i_lens) continue;
        if (i_trans < 0) i_trans = i; else i_labels = i;
    }
    if (i_trans >= 0 && i_labels >= 0 && sz[i_trans] > sz[i_labels]) {
        int t = i_trans; i_trans = i_labels; i_labels = t;
    }

    logits = (const float*)d_in[i_logits];
    trans  = (const float*)d_in[i_trans];
    labels = (const int*)  d_in[i_labels];
    lens   = (const int*)  d_in[i_lens];
    B = (int)sz[i_lens];
    L = (int)(sz[i_labels] / B);

    crf_prep<<<1, 64>>>(trans);
    crf_main<<<B, 64>>>(logits, trans, labels, lens, L);
    crf_reduce<<<1, 256>>>((float*)d_out, B);
}

// round 4
// speedup vs baseline: 1.4401x; 1.4401x over previous
#include <cuda_runtime.h>
#include <cstdint>

// CRF NLL: B=1024, L=512, T=50 (48 tags + START(48) + STOP(49))
#define TT        50
#define START_TAG 48
#define STOP_TAG  49
#define NEG_VAL   (-10000.0f)
#define PADNEG    (-1e30f)

// __device__ scratch (allocation-free rule)
__device__ __align__(16) float g_E[64 * 52];   // exp(trans[y][x]-M[y]); zero outside 50x50
__device__ float g_M[64];                      // row max of transitions
__device__ float g_tstart[64];                 // trans[y][START]
__device__ float g_tstop[64];                  // trans[STOP][y]
__device__ float g_partial[2048];              // per-batch (partition - gold)

// ---- packed f32x2 helpers -------------------------------------------------
static __device__ __forceinline__ void fma2(unsigned long long& acc,
                                            unsigned long long e,
                                            unsigned long long a) {
#if defined(__CUDA_ARCH__) && (__CUDA_ARCH__ >= 1000)
    asm("fma.rn.f32x2 %0, %1, %2, %0;" : "+l"(acc) : "l"(e), "l"(a));
#else
    float2 A, E, C;
    asm("mov.b64 {%0,%1}, %2;" : "=f"(E.x), "=f"(E.y) : "l"(e));
    asm("mov.b64 {%0,%1}, %2;" : "=f"(A.x), "=f"(A.y) : "l"(a));
    asm("mov.b64 {%0,%1}, %2;" : "=f"(C.x), "=f"(C.y) : "l"(acc));
    C.x = fmaf(E.x, A.x, C.x);
    C.y = fmaf(E.y, A.y, C.y);
    asm("mov.b64 %0, {%1,%2};" : "=l"(acc) : "f"(C.x), "f"(C.y));
#endif
}

static __device__ __forceinline__ float2 u2f(unsigned long long v) {
    float2 r;
    asm("mov.b64 {%0,%1}, %2;" : "=f"(r.x), "=f"(r.y) : "l"(v));
    return r;
}

static __device__ __forceinline__ float rcp_fast(float x) {
    float r;
    asm("rcp.approx.f32 %0, %1;" : "=f"(r) : "f"(x));
    return r;
}

// ---------------------------------------------------------------------------
// Kernel 1: precompute E, M, tstart, tstop (one 256-thread block)
// ---------------------------------------------------------------------------
__global__ void crf_prep(const float* __restrict__ trans) {
    __shared__ float sM[64];
    const int tid = threadIdx.x;

    if (tid < 64) {
        float M;
        if (tid < TT) {
            M = PADNEG;
            #pragma unroll 5
            for (int x = 0; x < TT; ++x)
                M = fmaxf(M, __ldg(&trans[tid * TT + x]));
        } else {
            M = 0.0f;
        }
        sM[tid] = M;
        g_M[tid] = M;
        g_tstart[tid] = (tid < TT) ? __ldg(&trans[tid * TT + START_TAG]) : PADNEG;
        g_tstop[tid]  = (tid < TT) ? __ldg(&trans[STOP_TAG * TT + tid])  : PADNEG;
    }
    __syncthreads();

    for (int i = tid; i < 64 * 52; i += 256) {
        int y = i / 52;
        int x = i - y * 52;
        float e = 0.0f;
        if (y < TT && x < TT) e = __expf(__ldg(&trans[y * TT + x]) - sM[y]);
        g_E[i] = e;
    }
}

// ---------------------------------------------------------------------------
// Kernel 2: ONE WARP per batch element; thread owns tags (2i, 2i+1).
// Exp-domain forward recurrence with LAGGED reference-tag normalization:
//   v_y(l) = e_y(l) * dot_y(l);  u_y(l) = v_y(l) * r;  r = 1/v_0(l-1)
//   m accumulates log(w) at the step where r=1/w is APPLIED, so the
//   invariant alpha_y(l) = m + log u_y(l) holds after every step.
// The shfl/rcp/log for the factor overlap the NEXT step's FMA chain.
// ---------------------------------------------------------------------------
__global__ __launch_bounds__(32) void crf_main(
    const float* __restrict__ logits,
    const float* __restrict__ trans,
    const int*   __restrict__ labels,
    const int*   __restrict__ lens,
    int L)
{
    const int b    = blockIdx.x;
    const int lane = threadIdx.x;

    const int len = lens[b];
    const float* lg  = logits + (size_t)b * (size_t)L * TT;
    const int*   lab = labels + (size_t)b * L;

    __shared__ __align__(16) float s_a[2][64];   // double buffer: 1 syncwarp/step is race-free

    // ---- gold score (emission + transition), warp-parallel over l ----
    float acc = 0.0f;
    for (int l = lane; l < len; l += 32) {
        int cur = lab[l];
        acc += __ldg(&lg[l * TT + cur]);
        int prev = (l == 0) ? START_TAG : lab[l - 1];
        acc += __ldg(&trans[cur * TT + prev]);
    }
    if (lane == 0) acc += __ldg(&trans[STOP_TAG * TT + lab[len - 1]]);
    #pragma unroll
    for (int o = 16; o > 0; o >>= 1)
        acc += __shfl_xor_sync(0xFFFFFFFFu, acc, o);
    const float gold = acc;

    // ---- per-thread tag pair + constants ----
    const int t0  = 2 * lane;
    const int t1  = t0 + 1;
    const int t0c = (t0 < TT - 2) ? t0 : (TT - 2);  // clamp: float2 load stays in-bounds

    // E rows packed as f32x2 pairs (26 per tag) in registers
    unsigned long long E0[26], E1[26];
    {
        const unsigned long long* p0 = (const unsigned long long*)&g_E[t0 * 52];
        const unsigned long long* p1 = (const unsigned long long*)&g_E[t1 * 52];
        #pragma unroll
        for (int j = 0; j < 26; ++j) { E0[j] = p0[j]; E1[j] = p1[j]; }
    }
    const float M0  = g_M[t0];
    const float M1  = g_M[t1];
    const float ts0 = g_tstop[t0];
    const float ts1 = g_tstop[t1];

    // ---- step 0 closed form: alpha1[y] = lgt0[y] + trans[y][START]
    // (exact vs reference: its LSE flushes the exp(-1e4) cross terms to 0 in fp32)
    float2 lgv = *(const float2*)&lg[t0c];
    float a0 = lgv.x + g_tstart[t0];
    float a1 = lgv.y + g_tstart[t1];

    float m  = __shfl_sync(0xFFFFFFFFu, a0, 0);
    float u0 = __expf(a0 - m);          // pad tags: exp(-1e30 - m) = 0
    float u1 = __expf(a1 - m);

    // lagged-normalization state: first iteration applies r=1 (log_w=0)
    float r_cur = 1.0f, logw_cur = 0.0f;

    // logits prefetch pipeline, depth 4 (register rotation)
    float2 q0, q1, q2, q3;
    q0 = q1 = q2 = q3 = make_float2(0.f, 0.f);
    if (1 < len) q0 = *(const float2*)&lg[1 * TT + t0c];
    if (2 < len) q1 = *(const float2*)&lg[2 * TT + t0c];
    if (3 < len) q2 = *(const float2*)&lg[3 * TT + t0c];
    if (4 < len) q3 = *(const float2*)&lg[4 * TT + t0c];

    // ---- steps 1..len-1 ----
    for (int l = 1; l < len; ++l) {
        float2 cur = q0;
        q0 = q1; q1 = q2; q2 = q3;
        int lp = l + 4;
        if (lp < len) q3 = *(const float2*)&lg[lp * TT + t0c];

        float e0 = __expf(cur.x + M0);   // off the serial chain (uses prefetched logit)
        float e1 = __expf(cur.y + M1);

        float* buf = s_a[l & 1];
        *(float2*)&buf[t0] = make_float2(u0, u1);
        __syncwarp();

        // dot_y = E[y] . u  via packed f32x2 FMAs (4 accumulators per tag)
        unsigned long long d00 = 0ull, d01 = 0ull, d02 = 0ull, d03 = 0ull;
        unsigned long long d10 = 0ull, d11 = 0ull, d12 = 0ull, d13 = 0ull;
        #pragma unroll
        for (int j = 0; j < 13; ++j) {
            ulonglong2 av = *(const ulonglong2*)&buf[4 * j];
            if (j & 1) {
                fma2(d01, E0[2 * j], av.x); fma2(d03, E0[2 * j + 1], av.y);
                fma2(d11, E1[2 * j], av.x); fma2(d13, E1[2 * j + 1], av.y);
            } else {
                fma2(d00, E0[2 * j], av.x); fma2(d02, E0[2 * j + 1], av.y);
                fma2(d10, E1[2 * j], av.x); fma2(d12, E1[2 * j + 1], av.y);
            }
        }
        float2 p0 = u2f(d00), p1 = u2f(d01), p2 = u2f(d02), p3 = u2f(d03);
        float dot0 = ((p0.x + p0.y) + (p1.x + p1.y)) + ((p2.x + p2.y) + (p3.x + p3.y));
        float2 s0 = u2f(d10), s1 = u2f(d11), s2 = u2f(d12), s3 = u2f(d13);
        float dot1 = ((s0.x + s0.y) + (s1.x + s1.y)) + ((s2.x + s2.y) + (s3.x + s3.y));

        float v0 = e0 * dot0;
        float v1 = e1 * dot1;

        // apply the LAGGED factor (r_cur/logw_cur were produced at step l-1)
        u0 = v0 * r_cur;
        u1 = v1 * r_cur;
        m += logw_cur;

        // prepare next step's factor from THIS step's lane-0 v (overlaps next FMAs)
        float w = __shfl_sync(0xFFFFFFFFu, v0, 0);
        r_cur    = rcp_fast(w);
        logw_cur = __logf(w);
    }
    // Pending (r_cur, logw_cur) was never applied -> invariant already holds.

    // ---- partition = m + LSE_y(log u_y + tstop_y) ----
    float fv0 = __logf(u0) + ts0;       // u=0 -> -inf ; pad tags -> -inf
    float fv1 = __logf(u1) + ts1;
    float mx = fmaxf(fv0, fv1);
    #pragma unroll
    for (int o = 16; o > 0; o >>= 1)
        mx = fmaxf(mx, __shfl_xor_sync(0xFFFFFFFFu, mx, o));
    float ssum = __expf(fv0 - mx) + __expf(fv1 - mx);
    #pragma unroll
    for (int o = 16; o > 0; o >>= 1)
        ssum += __shfl_xor_sync(0xFFFFFFFFu, ssum, o);

    if (lane == 0) {
        float partition = m + mx + __logf(ssum);
        g_partial[b] = partition - gold;
    }
}

// ---------------------------------------------------------------------------
// Kernel 3: deterministic final reduction -> scalar mean
// ---------------------------------------------------------------------------
__global__ void crf_reduce(float* __restrict__ out, int B) {
    __shared__ float s[256];
    float a = 0.0f;
    for (int i = threadIdx.x; i < B; i += 256) a += g_partial[i];
    s[threadIdx.x] = a;
    __syncthreads();
    #pragma unroll
    for (int st = 128; st > 0; st >>= 1) {
        if (threadIdx.x < st) s[threadIdx.x] += s[threadIdx.x + st];
        __syncthreads();
    }
    if (threadIdx.x == 0) out[0] = s[0] / (float)B;
}

// ---------------------------------------------------------------------------
extern "C" void kernel_launch(void* const* d_in, const int* in_sizes, int n_in,
                              void* d_out, int out_size)
{
    // Identify inputs by element count:
    //   logits 26,214,400 | labels 524,288 | transitions 2,500 | lens 1,024
    long long sz[8];
    for (int i = 0; i < n_in && i < 8; ++i) sz[i] = in_sizes[i];

    int i_logits = -1, i_trans = -1, i_labels = -1, i_lens = -1;
    long long mx = -1, mn = (long long)1 << 62;
    for (int i = 0; i < n_in; ++i) {
        if (sz[i] > mx) { mx = sz[i]; i_logits = i; }
        if (sz[i] < mn) { mn = sz[i]; i_lens = i; }
    }
    for (int i = 0; i < n_in; ++i) {
        if (i == i_logits || i == i_lens) continue;
        if (i_trans < 0) i_trans = i; else i_labels = i;
    }
    if (i_trans >= 0 && i_labels >= 0 && sz[i_trans] > sz[i_labels]) {
        int t = i_trans; i_trans = i_labels; i_labels = t;
    }

    const float* logits = (const float*)d_in[i_logits];
    const float* trans  = (const float*)d_in[i_trans];
    const int*   labels = (const int*)  d_in[i_labels];
    const int*   lens   = (const int*)  d_in[i_lens];
    int B = (int)sz[i_lens];
    int L = (int)(sz[i_labels] / B);

    crf_prep<<<1, 256>>>(trans);
    crf_main<<<B, 32>>>(logits, trans, labels, lens, L);
    crf_reduce<<<1, 256>>>((float*)d_out, B);
}

// round 5
// speedup vs baseline: 1.9473x; 1.3522x over previous
#include <cuda_runtime.h>
#include <cstdint>

// CRF NLL: B=1024, L=512, T=50 (48 real tags + START(48) + STOP(49)).
// Active set is 48 tags: u[START]==0 after step0 (e_START = exp(logit-1e4) = 0),
// E[:,STOP]==0, and tag STOP's final weight trans[STOP][STOP]=-1e4 flushes.
#define TT        50
#define NACT      48
#define START_TAG 48
#define STOP_TAG  49
#define PADNEG    (-1e30f)

__device__ int   g_perm[1024];     // slot -> batch permutation (length-balanced)
__device__ float g_partial[1024];  // per-batch (partition - gold)

// ---- packed f32x2 helpers -------------------------------------------------
static __device__ __forceinline__ void fma2(unsigned long long& acc,
                                            unsigned long long e,
                                            unsigned long long a) {
    asm("fma.rn.f32x2 %0, %1, %2, %0;" : "+l"(acc) : "l"(e), "l"(a));
}
static __device__ __forceinline__ unsigned long long add2(unsigned long long a,
                                                          unsigned long long b) {
    unsigned long long r;
    asm("add.rn.f32x2 %0, %1, %2;" : "=l"(r) : "l"(a), "l"(b));
    return r;
}
static __device__ __forceinline__ float2 u2f(unsigned long long v) {
    float2 r;
    asm("mov.b64 {%0,%1}, %2;" : "=f"(r.x), "=f"(r.y) : "l"(v));
    return r;
}
static __device__ __forceinline__ unsigned long long pack2(float lo, float hi) {
    unsigned long long v;
    asm("mov.b64 %0, {%1,%2};" : "=l"(v) : "f"(lo), "f"(hi));
    return v;
}
static __device__ __forceinline__ float rcp_fast(float x) {
    float r;
    asm("rcp.approx.f32 %0, %1;" : "=f"(r) : "f"(x));
    return r;
}

// ---------------------------------------------------------------------------
// Kernel 1: bitonic sort lens (ascending) + length-balanced slot permutation.
// Co-SMSP block pairs are (bid, bid+592) under classic placement; pair slot b
// (desc rank b) with slot b+592 (desc rank 1023-b) so pair-sums ~ constant.
// ---------------------------------------------------------------------------
__global__ void crf_sched(const int* __restrict__ lens, int B) {
    __shared__ int skey[1024];
    __shared__ int sidx[1024];
    const int t = threadIdx.x;

    if (B == 1024) {
        skey[t] = lens[t];
        sidx[t] = t;
        __syncthreads();
        for (int k = 2; k <= 1024; k <<= 1) {
            for (int j = k >> 1; j > 0; j >>= 1) {
                int ixj = t ^ j;
                if (ixj > t) {
                    bool up = ((t & k) == 0);
                    int ka = skey[t], kb = skey[ixj];
                    bool sw = up ? (ka > kb) : (ka < kb);
                    if (sw) {
                        int ia = sidx[t], ib = sidx[ixj];
                        skey[t] = kb; skey[ixj] = ka;
                        sidx[t] = ib; sidx[ixj] = ia;
                    }
                }
                __syncthreads();
            }
        }
        // slot t gets descending rank r; sorted ascending => desc rank r is sidx[1023-r]
        int r = (t < 592) ? t : (1615 - t);
        g_perm[t] = sidx[1023 - r];
    } else {
        if (t < B) g_perm[t] = t;   // fallback: identity
    }
}

// ---------------------------------------------------------------------------
// One forward step (exp-domain, lagged reference-tag normalization).
// ---------------------------------------------------------------------------
static __device__ __forceinline__ void crf_step(
    float2 cur, float* __restrict__ buf, int t0,
    const unsigned long long* __restrict__ E0,
    const unsigned long long* __restrict__ E1,
    float M0, float M1,
    float& u0, float& u1, float& m, float& r_cur, float& logw_cur)
{
    float e0 = __expf(cur.x + M0);     // off-chain (prefetched logit)
    float e1 = __expf(cur.y + M1);

    *(float2*)&buf[t0] = make_float2(u0, u1);
    __syncwarp();

    unsigned long long d0 = 0ull, d1 = 0ull, d2 = 0ull, d3 = 0ull;
    unsigned long long f0 = 0ull, f1 = 0ull, f2 = 0ull, f3 = 0ull;
    #pragma unroll
    for (int j = 0; j < 6; ++j) {
        ulonglong2 a0 = *(const ulonglong2*)&buf[8 * j];        // u[8j..8j+3]
        ulonglong2 a1 = *(const ulonglong2*)&buf[8 * j + 4];    // u[8j+4..8j+7]
        fma2(d0, E0[4 * j + 0], a0.x); fma2(d1, E0[4 * j + 1], a0.y);
        fma2(d2, E0[4 * j + 2], a1.x); fma2(d3, E0[4 * j + 3], a1.y);
        fma2(f0, E1[4 * j + 0], a0.x); fma2(f1, E1[4 * j + 1], a0.y);
        fma2(f2, E1[4 * j + 2], a1.x); fma2(f3, E1[4 * j + 3], a1.y);
    }
    float2 sd = u2f(add2(add2(d0, d1), add2(d2, d3)));
    float dot0 = sd.x + sd.y;
    float2 sf = u2f(add2(add2(f0, f1), add2(f2, f3)));
    float dot1 = sf.x + sf.y;

    float v0 = e0 * dot0;
    float v1 = e1 * dot1;

    u0 = v0 * r_cur;                   // apply LAGGED factor from step l-1
    u1 = v1 * r_cur;
    m += logw_cur;

    float w = __shfl_sync(0xFFFFFFFFu, v0, 0);
    r_cur    = rcp_fast(w);            // next step's factor (overlaps next FMAs)
    logw_cur = __logf(w);
}

// ---------------------------------------------------------------------------
// Kernel 2: one warp per batch element (slot -> batch via g_perm).
// Thread owns tags (2*lane, 2*lane+1); lanes 24..31 are dead padding.
// ---------------------------------------------------------------------------
__global__ __launch_bounds__(32) void crf_main(
    const float* __restrict__ logits,
    const float* __restrict__ trans,
    const int*   __restrict__ labels,
    const int*   __restrict__ lens,
    int L)
{
    const int b    = g_perm[blockIdx.x];
    const int lane = threadIdx.x;

    const int len = lens[b];
    const float* lg  = logits + (size_t)b * (size_t)L * TT;
    const int*   lab = labels + (size_t)b * L;

    __shared__ __align__(16) float s_a[2][64];   // double buffer

    // ---- gold score (emission + transition), warp-parallel over l ----
    float acc = 0.0f;
    for (int l = lane; l < len; l += 32) {
        int cur = lab[l];
        acc += __ldg(&lg[l * TT + cur]);
        int prev = (l == 0) ? START_TAG : lab[l - 1];
        acc += __ldg(&trans[cur * TT + prev]);
    }
    if (lane == 0) acc += __ldg(&trans[STOP_TAG * TT + lab[len - 1]]);
    #pragma unroll
    for (int o = 16; o > 0; o >>= 1)
        acc += __shfl_xor_sync(0xFFFFFFFFu, acc, o);
    const float gold = acc;

    // ---- per-thread tag pair; build E rows from trans (L1-resident, 10KB) ----
    const int t0  = 2 * lane;
    const int t1  = t0 + 1;
    const int t0c = (t0 < NACT) ? t0 : NACT;   // clamp: float2 logit load in-bounds
    const bool act = (t0 < NACT);

    float M0 = PADNEG, M1 = PADNEG;
    unsigned long long E0[24], E1[24];
    float tst0 = PADNEG, tst1 = PADNEG, ts0 = PADNEG, ts1 = PADNEG;

    if (act) {
        const float* r0 = trans + t0 * TT;
        const float* r1 = r0 + TT;
        #pragma unroll 8
        for (int x = 0; x < NACT; ++x) {
            M0 = fmaxf(M0, __ldg(&r0[x]));
            M1 = fmaxf(M1, __ldg(&r1[x]));
        }
        #pragma unroll
        for (int j = 0; j < 24; ++j) {
            E0[j] = pack2(__expf(__ldg(&r0[2 * j]) - M0),
                          __expf(__ldg(&r0[2 * j + 1]) - M0));
            E1[j] = pack2(__expf(__ldg(&r1[2 * j]) - M1),
                          __expf(__ldg(&r1[2 * j + 1]) - M1));
        }
        tst0 = __ldg(&r0[START_TAG]);
        tst1 = __ldg(&r1[START_TAG]);
        ts0  = __ldg(&trans[STOP_TAG * TT + t0]);
        ts1  = __ldg(&trans[STOP_TAG * TT + t1]);
    } else {
        #pragma unroll
        for (int j = 0; j < 24; ++j) { E0[j] = 0ull; E1[j] = 0ull; }
    }

    // ---- step 0 closed form: alpha1[y] = logit0[y] + trans[y][START] ----
    float2 lgv = *(const float2*)&lg[t0c];
    float a0 = lgv.x + tst0;           // inactive: -1e30 -> u = 0
    float a1 = lgv.y + tst1;

    float m  = __shfl_sync(0xFFFFFFFFu, a0, 0);
    float u0 = __expf(a0 - m);
    float u1 = __expf(a1 - m);

    float r_cur = 1.0f, logw_cur = 0.0f;

    // ---- steps 1..len-1: unroll-4 main loop (no clamps), scalar tail ----
    int l = 1;
    float2 q0, q1, q2, q3;
    if (len >= 9) {
        q0 = *(const float2*)&lg[1 * TT + t0c];
        q1 = *(const float2*)&lg[2 * TT + t0c];
        q2 = *(const float2*)&lg[3 * TT + t0c];
        q3 = *(const float2*)&lg[4 * TT + t0c];
        const float* pr = lg + 5 * TT + t0c;   // row l+4
        for (; l + 8 <= len; l += 4) {
            crf_step(q0, s_a[1], t0, E0, E1, M0, M1, u0, u1, m, r_cur, logw_cur);
            q0 = *(const float2*)(pr);
            crf_step(q1, s_a[0], t0, E0, E1, M0, M1, u0, u1, m, r_cur, logw_cur);
            q1 = *(const float2*)(pr + TT);
            crf_step(q2, s_a[1], t0, E0, E1, M0, M1, u0, u1, m, r_cur, logw_cur);
            q2 = *(const float2*)(pr + 2 * TT);
            crf_step(q3, s_a[0], t0, E0, E1, M0, M1, u0, u1, m, r_cur, logw_cur);
            q3 = *(const float2*)(pr + 3 * TT);
            pr += 4 * TT;
        }
    }
    for (; l < len; ++l) {              // <= 7 steps; l parity continues chain
        float2 c = *(const float2*)&lg[l * TT + t0c];
        crf_step(c, s_a[l & 1], t0, E0, E1, M0, M1, u0, u1, m, r_cur, logw_cur);
    }

    // ---- partition = m + LSE_y(log u_y + trans[STOP][y]) over active tags ----
    float fv0 = __logf(u0) + ts0;       // u=0 / inactive -> -inf
    float fv1 = __logf(u1) + ts1;
    float mx = fmaxf(fv0, fv1);
    #pragma unroll
    for (int o = 16; o > 0; o >>= 1)
        mx = fmaxf(mx, __shfl_xor_sync(0xFFFFFFFFu, mx, o));
    float ssum = __expf(fv0 - mx) + __expf(fv1 - mx);
    #pragma unroll
    for (int o = 16; o > 0; o >>= 1)
        ssum += __shfl_xor_sync(0xFFFFFFFFu, ssum, o);

    if (lane == 0) {
        float partition = m + mx + __logf(ssum);
        g_partial[b] = partition - gold;
    }
}

// ---------------------------------------------------------------------------
// Kernel 3: deterministic final reduction -> scalar mean
// ---------------------------------------------------------------------------
__global__ void crf_reduce(float* __restrict__ out, int B) {
    __shared__ float s[256];
    float a = 0.0f;
    for (int i = threadIdx.x; i < B; i += 256) a += g_partial[i];
    s[threadIdx.x] = a;
    __syncthreads();
    #pragma unroll
    for (int st = 128; st > 0; st >>= 1) {
        if (threadIdx.x < st) s[threadIdx.x] += s[threadIdx.x + st];
        __syncthreads();
    }
    if (threadIdx.x == 0) out[0] = s[0] / (float)B;
}

// ---------------------------------------------------------------------------
extern "C" void kernel_launch(void* const* d_in, const int* in_sizes, int n_in,
                              void* d_out, int out_size)
{
    // Identify inputs by element count:
    //   logits 26,214,400 | labels 524,288 | transitions 2,500 | lens 1,024
    long long sz[8];
    for (int i = 0; i < n_in && i < 8; ++i) sz[i] = in_sizes[i];

    int i_logits = -1, i_trans = -1, i_labels = -1, i_lens = -1;
    long long mx = -1, mn = (long long)1 << 62;
    for (int i = 0; i < n_in; ++i) {
        if (sz[i] > mx) { mx = sz[i]; i_logits = i; }
        if (sz[i] < mn) { mn = sz[i]; i_lens = i; }
    }
    for (int i = 0; i < n_in; ++i) {
        if (i == i_logits || i == i_lens) continue;
        if (i_trans < 0) i_trans = i; else i_labels = i;
    }
    if (i_trans >= 0 && i_labels >= 0 && sz[i_trans] > sz[i_labels]) {
        int t = i_trans; i_trans = i_labels; i_labels = t;
    }

    const float* logits = (const float*)d_in[i_logits];
    const float* trans  = (const float*)d_in[i_trans];
    const int*   labels = (const int*)  d_in[i_labels];
    const int*   lens   = (const int*)  d_in[i_lens];
    int B = (int)sz[i_lens];
    int L = (int)(sz[i_labels] / B);

    crf_sched<<<1, 1024>>>(lens, B);
    crf_main<<<B, 32>>>(logits, trans, labels, lens, L);
    crf_reduce<<<1, 256>>>((float*)d_out, B);
}

// round 6
// speedup vs baseline: 1.9854x; 1.0196x over previous
#include <cuda_runtime.h>
#include <cstdint>

// CRF NLL: B=1024, L=512, T=50 (48 real tags + START(48) + STOP(49)).
// Active set is 48 tags: u[START]==0 after step0 (e_START = exp(logit-1e4) = 0),
// E[:,STOP]==0, and STOP's final weight trans[STOP][STOP]=-1e4 flushes in fp32.
#define TT        50
#define NACT      48
#define START_TAG 48
#define STOP_TAG  49
#define PADNEG    (-1e30f)

__device__ int   g_idx[1024];      // descending-length rank -> batch index
__device__ float g_partial[1024];  // per-batch (partition - gold)

// ---- packed f32x2 helpers -------------------------------------------------
static __device__ __forceinline__ void fma2(unsigned long long& acc,
                                            unsigned long long e,
                                            unsigned long long a) {
    asm("fma.rn.f32x2 %0, %1, %2, %0;" : "+l"(acc) : "l"(e), "l"(a));
}
static __device__ __forceinline__ unsigned long long add2(unsigned long long a,
                                                          unsigned long long b) {
    unsigned long long r;
    asm("add.rn.f32x2 %0, %1, %2;" : "=l"(r) : "l"(a), "l"(b));
    return r;
}
static __device__ __forceinline__ float2 u2f(unsigned long long v) {
    float2 r;
    asm("mov.b64 {%0,%1}, %2;" : "=f"(r.x), "=f"(r.y) : "l"(v));
    return r;
}
static __device__ __forceinline__ unsigned long long pack2(float lo, float hi) {
    unsigned long long v;
    asm("mov.b64 %0, {%1,%2};" : "=l"(v) : "f"(lo), "f"(hi));
    return v;
}
static __device__ __forceinline__ float rcp_fast(float x) {
    float r;
    asm("rcp.approx.f32 %0, %1;" : "=f"(r) : "f"(x));
    return r;
}

// ---------------------------------------------------------------------------
// Kernel 1: rank-by-counting scheduler. 32 blocks x 32 threads; thread handles
// batch b = bid*32+lane, counts its descending rank (ties by index) and
// scatters g_idx[rank] = b. ~1024 smem-broadcast iterations per thread.
// ---------------------------------------------------------------------------
__global__ void crf_rank(const int* __restrict__ lens, int B) {
    __shared__ int sl[1024];
    const int lane = threadIdx.x;
    const int b = blockIdx.x * 32 + lane;

    if (B > 1024) {                      // fallback: identity schedule
        for (int i = b; i < B; i += gridDim.x * 32) g_idx[i] = i;
        return;
    }
    for (int i = lane; i < B; i += 32) sl[i] = lens[i];
    __syncthreads();

    if (b < B) {
        const int lb = sl[b];
        int r = 0;
        #pragma unroll 4
        for (int j = 0; j < B; ++j) {
            int lj = sl[j];
            r += (lj > lb) || ((lj == lb) && (j < b));
        }
        g_idx[r] = b;                    // deterministic permutation
    }
}

// ---------------------------------------------------------------------------
// One forward step (exp-domain, lagged reference-tag normalization).
//   v_y = e_y * dot_y ; u_y' = v_y * r ; r = 1/v_0(prev step) ;
//   m += log(w) when factor is applied  =>  alpha_y = m + log u_y invariant.
// ---------------------------------------------------------------------------
static __device__ __forceinline__ void crf_step(
    float2 cur, float* __restrict__ buf, int t0,
    const unsigned long long* __restrict__ E0,
    const unsigned long long* __restrict__ E1,
    float M0, float M1,
    float& u0, float& u1, float& m, float& r_cur, float& logw_cur)
{
    float e0 = __expf(cur.x + M0);       // off-chain (prefetched logit)
    float e1 = __expf(cur.y + M1);

    *(float2*)&buf[t0] = make_float2(u0, u1);
    __syncwarp();

    unsigned long long d0 = 0ull, d1 = 0ull, d2 = 0ull, d3 = 0ull;
    unsigned long long f0 = 0ull, f1 = 0ull, f2 = 0ull, f3 = 0ull;
    #pragma unroll
    for (int j = 0; j < 6; ++j) {
        ulonglong2 a0 = *(const ulonglong2*)&buf[8 * j];
        ulonglong2 a1 = *(const ulonglong2*)&buf[8 * j + 4];
        fma2(d0, E0[4 * j + 0], a0.x); fma2(d1, E0[4 * j + 1], a0.y);
        fma2(d2, E0[4 * j + 2], a1.x); fma2(d3, E0[4 * j + 3], a1.y);
        fma2(f0, E1[4 * j + 0], a0.x); fma2(f1, E1[4 * j + 1], a0.y);
        fma2(f2, E1[4 * j + 2], a1.x); fma2(f3, E1[4 * j + 3], a1.y);
    }
    float2 sd = u2f(add2(add2(d0, d1), add2(d2, d3)));
    float dot0 = sd.x + sd.y;
    float2 sf = u2f(add2(add2(f0, f1), add2(f2, f3)));
    float dot1 = sf.x + sf.y;

    float v0 = e0 * dot0;
    float v1 = e1 * dot1;

    u0 = v0 * r_cur;                     // apply LAGGED factor from prev step
    u1 = v1 * r_cur;
    m += logw_cur;

    float w = __shfl_sync(0xFFFFFFFFu, v0, 0);
    r_cur    = rcp_fast(w);              // next step's factor (overlaps next FMAs)
    logw_cur = __logf(w);
}

// ---------------------------------------------------------------------------
// Process one sequence end-to-end; writes g_partial[b].
// ---------------------------------------------------------------------------
static __device__ __forceinline__ void crf_seq(
    int b, const float* __restrict__ logits, const float* __restrict__ trans,
    const int* __restrict__ labels, const int* __restrict__ lens, int L,
    int lane, int t0, int t0c,
    const unsigned long long* __restrict__ E0,
    const unsigned long long* __restrict__ E1,
    float M0, float M1, float tst0, float tst1, float ts0, float ts1,
    float* __restrict__ s_a)             // [2][64]
{
    const int len = lens[b];
    const float* lg  = logits + (size_t)b * (size_t)L * TT;
    const int*   lab = labels + (size_t)b * L;

    // gold score (emission + transition), warp-parallel over l
    float acc = 0.0f;
    for (int l = lane; l < len; l += 32) {
        int cur = lab[l];
        acc += __ldg(&lg[l * TT + cur]);
        int prev = (l == 0) ? START_TAG : lab[l - 1];
        acc += __ldg(&trans[cur * TT + prev]);
    }
    if (lane == 0) acc += __ldg(&trans[STOP_TAG * TT + lab[len - 1]]);
    #pragma unroll
    for (int o = 16; o > 0; o >>= 1)
        acc += __shfl_xor_sync(0xFFFFFFFFu, acc, o);
    const float gold = acc;

    // step 0 closed form: alpha1[y] = logit0[y] + trans[y][START]
    float2 lgv = *(const float2*)&lg[t0c];
    float a0 = lgv.x + tst0;             // inactive lanes: -1e30 -> u = 0
    float a1 = lgv.y + tst1;

    float m  = __shfl_sync(0xFFFFFFFFu, a0, 0);
    float u0 = __expf(a0 - m);
    float u1 = __expf(a1 - m);

    float r_cur = 1.0f, logw_cur = 0.0f;

    // steps 1..len-1: unroll-4 main loop (static buffer parity), scalar tail
    int l = 1;
    float2 q0, q1, q2, q3;
    if (len >= 9) {
        q0 = *(const float2*)&lg[1 * TT + t0c];
        q1 = *(const float2*)&lg[2 * TT + t0c];
        q2 = *(const float2*)&lg[3 * TT + t0c];
        q3 = *(const float2*)&lg[4 * TT + t0c];
        const float* pr = lg + 5 * TT + t0c;
        for (; l + 8 <= len; l += 4) {
            crf_step(q0, s_a + 64, t0, E0, E1, M0, M1, u0, u1, m, r_cur, logw_cur);
            q0 = *(const float2*)(pr);
            crf_step(q1, s_a,      t0, E0, E1, M0, M1, u0, u1, m, r_cur, logw_cur);
            q1 = *(const float2*)(pr + TT);
            crf_step(q2, s_a + 64, t0, E0, E1, M0, M1, u0, u1, m, r_cur, logw_cur);
            q2 = *(const float2*)(pr + 2 * TT);
            crf_step(q3, s_a,      t0, E0, E1, M0, M1, u0, u1, m, r_cur, logw_cur);
            q3 = *(const float2*)(pr + 3 * TT);
            pr += 4 * TT;
        }
    }
    for (; l < len; ++l) {
        float2 c = *(const float2*)&lg[l * TT + t0c];
        crf_step(c, s_a + 64 * (l & 1), t0, E0, E1, M0, M1, u0, u1, m, r_cur, logw_cur);
    }

    // partition = m + LSE_y(log u_y + trans[STOP][y])
    float fv0 = __logf(u0) + ts0;
    float fv1 = __logf(u1) + ts1;
    float mx = fmaxf(fv0, fv1);
    #pragma unroll
    for (int o = 16; o > 0; o >>= 1)
        mx = fmaxf(mx, __shfl_xor_sync(0xFFFFFFFFu, mx, o));
    float ssum = __expf(fv0 - mx) + __expf(fv1 - mx);
    #pragma unroll
    for (int o = 16; o > 0; o >>= 1)
        ssum += __shfl_xor_sync(0xFFFFFFFFu, ssum, o);

    if (lane == 0) {
        float partition = m + mx + __logf(ssum);
        g_partial[b] = partition - gold;
    }
}

// ---------------------------------------------------------------------------
// Kernel 2: one warp per PAIR of sequences (rank w and rank B-1-w).
// Every warp runs ~ (513) total steps -> balance independent of placement.
// ---------------------------------------------------------------------------
__global__ __launch_bounds__(32) void crf_main(
    const float* __restrict__ logits,
    const float* __restrict__ trans,
    const int*   __restrict__ labels,
    const int*   __restrict__ lens,
    int L, int B)
{
    const int w    = blockIdx.x;
    const int lane = threadIdx.x;

    const int bA = g_idx[w];
    const int bB = g_idx[B - 1 - w];

    __shared__ __align__(16) float s_a[2 * 64];

    // per-thread tag pair; build E rows from trans (L1-resident, 10KB)
    const int t0  = 2 * lane;
    const int t1  = t0 + 1;
    const int t0c = (t0 < NACT) ? t0 : NACT;
    const bool act = (t0 < NACT);

    float M0 = PADNEG, M1 = PADNEG;
    unsigned long long E0[24], E1[24];
    float tst0 = PADNEG, tst1 = PADNEG, ts0 = PADNEG, ts1 = PADNEG;

    if (act) {
        const float* r0 = trans + t0 * TT;
        const float* r1 = r0 + TT;
        #pragma unroll 8
        for (int x = 0; x < NACT; ++x) {
            M0 = fmaxf(M0, __ldg(&r0[x]));
            M1 = fmaxf(M1, __ldg(&r1[x]));
        }
        #pragma unroll
        for (int j = 0; j < 24; ++j) {
            E0[j] = pack2(__expf(__ldg(&r0[2 * j]) - M0),
                          __expf(__ldg(&r0[2 * j + 1]) - M0));
            E1[j] = pack2(__expf(__ldg(&r1[2 * j]) - M1),
                          __expf(__ldg(&r1[2 * j + 1]) - M1));
        }
        tst0 = __ldg(&r0[START_TAG]);
        tst1 = __ldg(&r1[START_TAG]);
        ts0  = __ldg(&trans[STOP_TAG * TT + t0]);
        ts1  = __ldg(&trans[STOP_TAG * TT + t1]);
    } else {
        #pragma unroll
        for (int j = 0; j < 24; ++j) { E0[j] = 0ull; E1[j] = 0ull; }
    }

    crf_seq(bA, logits, trans, labels, lens, L, lane, t0, t0c,
            E0, E1, M0, M1, tst0, tst1, ts0, ts1, s_a);
    if (bB != bA)
        crf_seq(bB, logits, trans, labels, lens, L, lane, t0, t0c,
                E0, E1, M0, M1, tst0, tst1, ts0, ts1, s_a);
}

// ---------------------------------------------------------------------------
// Kernel 3: deterministic final reduction -> scalar mean
// ---------------------------------------------------------------------------
__global__ void crf_reduce(float* __restrict__ out, int B) {
    __shared__ float s[256];
    float a = 0.0f;
    for (int i = threadIdx.x; i < B; i += 256) a += g_partial[i];
    s[threadIdx.x] = a;
    __syncthreads();
    #pragma unroll
    for (int st = 128; st > 0; st >>= 1) {
        if (threadIdx.x < st) s[threadIdx.x] += s[threadIdx.x + st];
        __syncthreads();
    }
    if (threadIdx.x == 0) out[0] = s[0] / (float)B;
}

// ---------------------------------------------------------------------------
extern "C" void kernel_launch(void* const* d_in, const int* in_sizes, int n_in,
                              void* d_out, int out_size)
{
    // Identify inputs by element count:
    //   logits 26,214,400 | labels 524,288 | transitions 2,500 | lens 1,024
    long long sz[8];
    for (int i = 0; i < n_in && i < 8; ++i) sz[i] = in_sizes[i];

    int i_logits = -1, i_trans = -1, i_labels = -1, i_lens = -1;
    long long mx = -1, mn = (long long)1 << 62;
    for (int i = 0; i < n_in; ++i) {
        if (sz[i] > mx) { mx = sz[i]; i_logits = i; }
        if (sz[i] < mn) { mn = sz[i]; i_lens = i; }
    }
    for (int i = 0; i < n_in; ++i) {
        if (i == i_logits || i == i_lens) continue;
        if (i_trans < 0) i_trans = i; else i_labels = i;
    }
    if (i_trans >= 0 && i_labels >= 0 && sz[i_trans] > sz[i_labels]) {
        int t = i_trans; i_trans = i_labels; i_labels = t;
    }

    const float* logits = (const float*)d_in[i_logits];
    const float* trans  = (const float*)d_in[i_trans];
    const int*   labels = (const int*)  d_in[i_labels];
    const int*   lens   = (const int*)  d_in[i_lens];
    int B = (int)sz[i_lens];
    int L = (int)(sz[i_labels] / B);

    int rank_blocks = (B + 31) / 32;
    int nwarps = (B + 1) / 2;

    crf_rank<<<rank_blocks, 32>>>(lens, B);
    crf_main<<<nwarps, 32>>>(logits, trans, labels, lens, L, B);
    crf_reduce<<<1, 256>>>((float*)d_out, B);
}